// round 12
// baseline (speedup 1.0000x reference)
#include <cuda_runtime.h>
#include <cuda_fp16.h>
#include <cstdint>

#define HH 256
#define WW 256
#define HW 65536
#define C 64
#define O 64
#define B 16
#define NK 4
#define GROUPS 8

#define XSP2 328                 // half2 plane stride: 18*18=324 pad (==8 mod 32)
#define NPLANE2 32
#define A_TAP_HALVES 4096
#define A_TAP_BYTES  8192
#define SMEM_BYTES (NPLANE2 * XSP2 * 4 + 9 * A_TAP_BYTES)   // 41984+73728=115712

// ---- scratch ----
__device__ __half g_wt[B * 9 * O * C];    // fp16 weights, MMA-fragment-ordered
__device__ __half g_y[(long long)B * O * HW];  // pre-norm conv output (fp16)
__device__ float g_sum[B * GROUPS];
__device__ float g_sumsq[B * GROUPS];

__device__ __forceinline__ void mma_f16(float* d, const uint32_t* a,
                                        uint32_t b0, uint32_t b1) {
    asm("mma.sync.aligned.m16n8k16.row.col.f32.f16.f16.f32 "
        "{%0,%1,%2,%3}, {%4,%5,%6,%7}, {%8,%9}, {%0,%1,%2,%3};"
        : "+f"(d[0]), "+f"(d[1]), "+f"(d[2]), "+f"(d[3])
        : "r"(a[0]), "r"(a[1]), "r"(a[2]), "r"(a[3]), "r"(b0), "r"(b1));
}
__device__ __forceinline__ void cp_async16(uint32_t dst, const void* src) {
    asm volatile("cp.async.cg.shared.global [%0], [%1], 16;" :: "r"(dst), "l"(src));
}

// ============================================================================
// Kernel 0: softmax mix + modulate + demodulate -> fp16 fragment-ordered g_wt.
// Layout (halves): [b][tap][wo(2)][kt(4)][mt(2)][lane(32)][pos(8)]
// ============================================================================
__global__ void weight_kernel(const float* __restrict__ mod,
                              const float* __restrict__ kmod,
                              const float* __restrict__ cw) {
    int o = blockIdx.x, b = blockIdx.y, i = threadIdx.x;

    float k0 = kmod[b*NK], k1 = kmod[b*NK+1], k2 = kmod[b*NK+2], k3 = kmod[b*NK+3];
    float mx = fmaxf(fmaxf(k0, k1), fmaxf(k2, k3));
    float e0 = __expf(k0-mx), e1 = __expf(k1-mx), e2 = __expf(k2-mx), e3 = __expf(k3-mx);
    float inv = 1.0f / (e0+e1+e2+e3);
    float a0 = e0*inv, a1 = e1*inv, a2 = e2*inv, a3 = e3*inv;
    float mi = mod[b*C + i] + 1.0f;

    float wv[9], ss = 0.0f;
#pragma unroll
    for (int k = 0; k < 9; k++) {
        int base = (o*C + i)*9 + k;
        const int st = O*C*9;
        float v = a0*cw[base] + a1*cw[st+base] + a2*cw[2*st+base] + a3*cw[3*st+base];
        v *= mi;
        wv[k] = v; ss += v*v;
    }
#pragma unroll
    for (int off = 16; off; off >>= 1) ss += __shfl_xor_sync(~0u, ss, off);
    __shared__ float sh[2];
    if ((i & 31) == 0) sh[i>>5] = ss;
    __syncthreads();
    float innorm = rsqrtf(fmaxf(sh[0] + sh[1], 1e-8f));

    int wo = o >> 5, m5 = o & 31, mt = m5 >> 4, row = m5 & 15;
    int kt = i >> 4, kk = i & 15;
    int rA = ((kk >= 8) ? 2 : 0) + ((row >= 8) ? 1 : 0);
    int lane = ((row & 7) << 2) | ((kk & 7) >> 1);
    int pos = rA * 2 + (kk & 1);

#pragma unroll
    for (int k = 0; k < 9; k++) {
        long long idx = (((((long long)(b*9 + k)*2 + wo)*4 + kt)*2 + mt)*32 + lane)*8 + pos;
        g_wt[idx] = __float2half_rn(wv[k] * innorm);
    }

    if (o == 0 && i < GROUPS) { g_sum[b*GROUPS+i] = 0.0f; g_sumsq[b*GROUPS+i] = 0.0f; }
}

// ============================================================================
// Kernel 1: fp16 tensor-core conv, all 9 taps smem-resident, barrier-free
// mainloop. grid (16,16,B), 256 thr = 8 warps, 2 CTAs/SM (115712 B smem).
// Output: fp16 to g_y + GN partial stats (fp32).
// ============================================================================
__global__ void __launch_bounds__(256, 2)
conv_kernel(const float* __restrict__ x) {
    extern __shared__ char smem[];
    __half2* xs2 = (__half2*)smem;                                // 32*XSP2
    __half* as_h = (__half*)(smem + NPLANE2 * XSP2 * 4);          // 9*A_TAP_HALVES
    __shared__ float gsum[GROUPS], gsq[GROUPS];

    int b = blockIdx.z;
    int h0 = blockIdx.y * 16, w0 = blockIdx.x * 16;
    int tid = threadIdx.x, wid = tid >> 5, lane = tid & 31;
    int wo = wid & 1;        // O half
    int wn = wid >> 1;       // pixel quarter: tile rows 4*wn..4*wn+3
    int g2 = lane >> 2;      // 0..7
    int qp = lane & 3;       // 0..3

    if (tid < GROUPS) { gsum[tid] = 0.0f; gsq[tid] = 0.0f; }

    const __half* wtb = g_wt + (long long)b * 9 * O * C;
    uint32_t as_smem;
    asm("{ .reg .u64 t; cvta.to.shared.u64 t, %1; cvt.u32.u64 %0, t; }"
        : "=r"(as_smem) : "l"((void*)as_h));

    // load ALL 9 A tap buffers (73728 B = 4608 chunks, 18/thread)
#pragma unroll
    for (int j = 0; j < 18; j++) {
        int ch = tid + j * 256;
        cp_async16(as_smem + ch * 16, wtb + ch * 8);
    }
    asm volatile("cp.async.commit_group;");

    // ---- stage x halo tile as channel-pair half2 (zero padded) ----
    const float* xb = x + (long long)b * C * HW;
    for (int idx = tid; idx < NPLANE2 * 324; idx += 256) {
        int ci2 = idx / 324;
        int rem = idx - ci2 * 324;
        int rr = rem / 18, cc = rem - rr * 18;
        int gh = h0 + rr - 1, gw = w0 + cc - 1;
        float v0 = 0.0f, v1 = 0.0f;
        if ((unsigned)gh < HH && (unsigned)gw < WW) {
            const float* p = xb + (2 * ci2) * HW + gh * WW + gw;
            v0 = p[0]; v1 = p[HW];
        }
        xs2[ci2 * XSP2 + rr * 18 + cc] = __floats2half2_rn(v0, v1);
    }
    asm volatile("cp.async.wait_group 0;");
    __syncthreads();   // the ONLY mainloop barrier

    float acc[2][8][4];
#pragma unroll
    for (int mt = 0; mt < 2; mt++)
#pragma unroll
        for (int nt = 0; nt < 8; nt++)
#pragma unroll
            for (int r = 0; r < 4; r++) acc[mt][nt][r] = 0.0f;

#pragma unroll 1
    for (int tap = 0; tap < 9; tap++) {
        int kh = tap / 3, kw = tap - kh * 3;
        const uint4* a_base = (const uint4*)(as_h + tap * A_TAP_HALVES) +
                              (wo * 4) * 2 * 32 + lane;
        const __half2* b_base = xs2 + qp * XSP2 + (wn * 4 + kh) * 18 + kw + g2;

#pragma unroll
        for (int kt = 0; kt < 4; kt++) {
            uint4 af0 = a_base[(kt * 2 + 0) * 32];
            uint4 af1 = a_base[(kt * 2 + 1) * 32];
            const __half2* bp = b_base + kt * 8 * XSP2;
#pragma unroll
            for (int nt = 0; nt < 8; nt++) {
                int po = (nt >> 1) * 18 + (nt & 1) * 8;
                uint32_t b0 = *(const uint32_t*)(bp + po);
                uint32_t b1 = *(const uint32_t*)(bp + 4 * XSP2 + po);
                mma_f16(acc[0][nt], (const uint32_t*)&af0, b0, b1);
                mma_f16(acc[1][nt], (const uint32_t*)&af1, b0, b1);
            }
        }
    }

    // ---- store conv output (fp16) + GN partial stats (fp32) ----
    __half* yb = g_y + (long long)b * O * HW;
    float s[2][2] = {{0, 0}, {0, 0}}, s2[2][2] = {{0, 0}, {0, 0}};
#pragma unroll
    for (int mt = 0; mt < 2; mt++) {
#pragma unroll
        for (int nt = 0; nt < 8; nt++) {
            int gh = h0 + wn * 4 + (nt >> 1);
            int gw = w0 + (nt & 1) * 8 + 2 * qp;
            int o_lo = wo * 32 + mt * 16 + g2;
            float c0 = acc[mt][nt][0], c1 = acc[mt][nt][1];
            float c2 = acc[mt][nt][2], c3 = acc[mt][nt][3];
            *(__half2*)(yb + o_lo * HW + gh * WW + gw) = __floats2half2_rn(c0, c1);
            *(__half2*)(yb + (o_lo + 8) * HW + gh * WW + gw) = __floats2half2_rn(c2, c3);
            s[mt][0] += c0 + c1;  s2[mt][0] += c0 * c0 + c1 * c1;
            s[mt][1] += c2 + c3;  s2[mt][1] += c2 * c2 + c3 * c3;
        }
    }
#pragma unroll
    for (int off = 16; off; off >>= 1) {
#pragma unroll
        for (int mt = 0; mt < 2; mt++)
#pragma unroll
            for (int hi = 0; hi < 2; hi++) {
                s[mt][hi]  += __shfl_xor_sync(~0u, s[mt][hi], off);
                s2[mt][hi] += __shfl_xor_sync(~0u, s2[mt][hi], off);
            }
    }
    if (lane == 0) {
#pragma unroll
        for (int mt = 0; mt < 2; mt++)
#pragma unroll
            for (int hi = 0; hi < 2; hi++) {
                int g = wo * 4 + mt * 2 + hi;
                atomicAdd(&gsum[g], s[mt][hi]);
                atomicAdd(&gsq[g], s2[mt][hi]);
            }
    }
    __syncthreads();
    if (tid < GROUPS) {
        atomicAdd(&g_sum[b * GROUPS + tid], gsum[tid]);
        atomicAdd(&g_sumsq[b * GROUPS + tid], gsq[tid]);
    }
}

// ============================================================================
// Kernel 2: GroupNorm finalize + SiLU: read fp16 g_y, write fp32 d_out.
// ============================================================================
__global__ void norm_kernel(float* __restrict__ out,
                            const float* __restrict__ gamma,
                            const float* __restrict__ beta) {
    long long i = (long long)blockIdx.x * blockDim.x + threadIdx.x;
    long long base = i * 4;
    int cidx = (int)(base >> 16);
    int b = cidx >> 6, c = cidx & 63, g = c >> 3;

    const float invN = 1.0f / (8.0f * HH * WW);
    float mean = g_sum[b * GROUPS + g] * invN;
    float var = g_sumsq[b * GROUPS + g] * invN - mean * mean;
    float istd = rsqrtf(var + 1e-5f);
    float ga = gamma[c], be = beta[c];

    const __half2* hp = (const __half2*)(g_y + base);
    float2 u0 = __half22float2(hp[0]);
    float2 u1 = __half22float2(hp[1]);
    float vv[4] = {u0.x, u0.y, u1.x, u1.y};
    float4 r;
    float* rp = &r.x;
#pragma unroll
    for (int k = 0; k < 4; k++) {
        float t = (vv[k] - mean) * istd * ga + be;
        rp[k] = t / (1.0f + __expf(-t));
    }
    *(float4*)&out[base] = r;
}

// ============================================================================
extern "C" void kernel_launch(void* const* d_in, const int* in_sizes, int n_in,
                              void* d_out, int out_size) {
    const float* x     = (const float*)d_in[0];
    const float* mod   = (const float*)d_in[1];
    const float* kmod  = (const float*)d_in[2];
    const float* cw    = (const float*)d_in[3];
    const float* gamma = (const float*)d_in[4];
    const float* beta  = (const float*)d_in[5];
    float* out = (float*)d_out;

    cudaFuncSetAttribute(conv_kernel,
                         cudaFuncAttributeMaxDynamicSharedMemorySize, SMEM_BYTES);

    weight_kernel<<<dim3(O, B), 64>>>(mod, kmod, cw);
    conv_kernel<<<dim3(16, 16, B), 256, SMEM_BYTES>>>(x);
    norm_kernel<<<(B * O * HW / 4) / 256, 256>>>(out, gamma, beta);
}

// round 13
// speedup vs baseline: 1.3442x; 1.3442x over previous
#include <cuda_runtime.h>
#include <cuda_fp16.h>
#include <cstdint>

#define HH 256
#define WW 256
#define HW 65536
#define C 64
#define O 64
#define B 16
#define NK 4
#define GROUPS 8

#define XSP2 328                 // half2 plane stride (==8 mod 32, conflict-free)
#define NPLANE2 32
#define SMEM_BYTES (NPLANE2 * XSP2 * 4)   // 41984

// ---- scratch ----
__device__ __half g_wt[B * 9 * O * C];          // fp16 weights, fragment-ordered
__device__ uint32_t g_y[(B * O * HW) / 2];      // packed half2 y, warp-linear layout
__device__ float g_sum[B * GROUPS];
__device__ float g_sumsq[B * GROUPS];

__device__ __forceinline__ void mma_f16(float* d, const uint32_t* a,
                                        uint32_t b0, uint32_t b1) {
    asm("mma.sync.aligned.m16n8k16.row.col.f32.f16.f16.f32 "
        "{%0,%1,%2,%3}, {%4,%5,%6,%7}, {%8,%9}, {%0,%1,%2,%3};"
        : "+f"(d[0]), "+f"(d[1]), "+f"(d[2]), "+f"(d[3])
        : "r"(a[0]), "r"(a[1]), "r"(a[2]), "r"(a[3]), "r"(b0), "r"(b1));
}
__device__ __forceinline__ uint32_t packh2(float a, float b) {
    __half2 h = __floats2half2_rn(a, b);
    return *(uint32_t*)&h;
}

// ============================================================================
// Kernel 0: softmax mix + modulate + demodulate -> fp16 fragment-ordered g_wt.
// Layout (halves): [b][tap][wo(2)][kt(4)][mt(2)][lane(32)][pos(8)]
// ============================================================================
__global__ void weight_kernel(const float* __restrict__ mod,
                              const float* __restrict__ kmod,
                              const float* __restrict__ cw) {
    int o = blockIdx.x, b = blockIdx.y, i = threadIdx.x;

    float k0 = kmod[b*NK], k1 = kmod[b*NK+1], k2 = kmod[b*NK+2], k3 = kmod[b*NK+3];
    float mx = fmaxf(fmaxf(k0, k1), fmaxf(k2, k3));
    float e0 = __expf(k0-mx), e1 = __expf(k1-mx), e2 = __expf(k2-mx), e3 = __expf(k3-mx);
    float inv = 1.0f / (e0+e1+e2+e3);
    float a0 = e0*inv, a1 = e1*inv, a2 = e2*inv, a3 = e3*inv;
    float mi = mod[b*C + i] + 1.0f;

    float wv[9], ss = 0.0f;
#pragma unroll
    for (int k = 0; k < 9; k++) {
        int base = (o*C + i)*9 + k;
        const int st = O*C*9;
        float v = a0*cw[base] + a1*cw[st+base] + a2*cw[2*st+base] + a3*cw[3*st+base];
        v *= mi;
        wv[k] = v; ss += v*v;
    }
#pragma unroll
    for (int off = 16; off; off >>= 1) ss += __shfl_xor_sync(~0u, ss, off);
    __shared__ float sh[2];
    if ((i & 31) == 0) sh[i>>5] = ss;
    __syncthreads();
    float innorm = rsqrtf(fmaxf(sh[0] + sh[1], 1e-8f));

    int wo = o >> 5, m5 = o & 31, mt = m5 >> 4, row = m5 & 15;
    int kt = i >> 4, kk = i & 15;
    int rA = ((kk >= 8) ? 2 : 0) + ((row >= 8) ? 1 : 0);
    int lane = ((row & 7) << 2) | ((kk & 7) >> 1);
    int pos = rA * 2 + (kk & 1);

#pragma unroll
    for (int k = 0; k < 9; k++) {
        long long idx = (((((long long)(b*9 + k)*2 + wo)*4 + kt)*2 + mt)*32 + lane)*8 + pos;
        g_wt[idx] = __float2half_rn(wv[k] * innorm);
    }

    if (o == 0 && i < GROUPS) { g_sum[b*GROUPS+i] = 0.0f; g_sumsq[b*GROUPS+i] = 0.0f; }
}

// ============================================================================
// Kernel 1: fp16 tensor-core conv. A frags via LDG.128 (L1/L2-resident g_wt),
// barrier-free mainloop, fp16 warp-linear y stores. grid (16,16,B), 256 thr.
// ============================================================================
__global__ void __launch_bounds__(256, 2)
conv_kernel(const float* __restrict__ x) {
    extern __shared__ char smem[];
    __half2* xs2 = (__half2*)smem;
    __shared__ float gsum[GROUPS], gsq[GROUPS];

    int b = blockIdx.z;
    int h0 = blockIdx.y * 16, w0 = blockIdx.x * 16;
    int tid = threadIdx.x, wid = tid >> 5, lane = tid & 31;
    int wo = wid & 1;        // O half
    int wn = wid >> 1;       // pixel quarter: tile rows 4*wn..4*wn+3
    int g2 = lane >> 2;      // 0..7
    int qp = lane & 3;       // 0..3

    if (tid < GROUPS) { gsum[tid] = 0.0f; gsq[tid] = 0.0f; }

    // ---- stage x halo tile as channel-pair half2 (zero padded) ----
    const float* xb = x + (long long)b * C * HW;
    for (int idx = tid; idx < NPLANE2 * 324; idx += 256) {
        int ci2 = idx / 324;
        int rem = idx - ci2 * 324;
        int rr = rem / 18, cc = rem - rr * 18;
        int gh = h0 + rr - 1, gw = w0 + cc - 1;
        float v0 = 0.0f, v1 = 0.0f;
        if ((unsigned)gh < HH && (unsigned)gw < WW) {
            const float* p = xb + (2 * ci2) * HW + gh * WW + gw;
            v0 = p[0]; v1 = p[HW];
        }
        xs2[ci2 * XSP2 + rr * 18 + cc] = __floats2half2_rn(v0, v1);
    }
    __syncthreads();   // the ONLY barrier before epilogue

    float acc[2][8][4];
#pragma unroll
    for (int mt = 0; mt < 2; mt++)
#pragma unroll
        for (int nt = 0; nt < 8; nt++)
#pragma unroll
            for (int r = 0; r < 4; r++) acc[mt][nt][r] = 0.0f;

    // A fragment base: uint4 index = ((((b*9+tap)*2+wo)*4+kt)*2+mt)*32 + lane
    const uint4* wf = (const uint4*)g_wt + ((b * 9 * 2 + wo) * 8) * 32 + lane;

#pragma unroll 1
    for (int tap = 0; tap < 9; tap++) {
        int kh = tap / 3, kw = tap - kh * 3;
        const uint4* a_base = wf + (tap * 2 * 8) * 32;   // tap stride: 2(wo)*8(kt,mt) rows
        const __half2* b_base = xs2 + qp * XSP2 + (wn * 4 + kh) * 18 + kw + g2;

#pragma unroll
        for (int kt = 0; kt < 4; kt++) {
            uint4 af0 = a_base[(kt * 2 + 0) * 32];
            uint4 af1 = a_base[(kt * 2 + 1) * 32];
            const __half2* bp = b_base + kt * 8 * XSP2;
#pragma unroll
            for (int nt = 0; nt < 8; nt++) {
                int po = (nt >> 1) * 18 + (nt & 1) * 8;
                uint32_t b0 = *(const uint32_t*)(bp + po);
                uint32_t b1 = *(const uint32_t*)(bp + 4 * XSP2 + po);
                mma_f16(acc[0][nt], (const uint32_t*)&af0, b0, b1);
                mma_f16(acc[1][nt], (const uint32_t*)&af1, b0, b1);
            }
        }
    }

    // ---- store y (fp16, warp-linear coalesced) + GN partial stats ----
    int cta_lin = (b * 16 + blockIdx.y) * 16 + blockIdx.x;
    uint32_t* ybuf = g_y + ((long long)cta_lin * 8 + wid) * 1024 + lane;
    float s[2][2] = {{0, 0}, {0, 0}}, s2[2][2] = {{0, 0}, {0, 0}};
#pragma unroll
    for (int mt = 0; mt < 2; mt++) {
#pragma unroll
        for (int nt = 0; nt < 8; nt++) {
            int slot = (mt * 8 + nt) * 2;
            float c0 = acc[mt][nt][0], c1 = acc[mt][nt][1];
            float c2 = acc[mt][nt][2], c3 = acc[mt][nt][3];
            ybuf[slot * 32] = packh2(c0, c1);
            ybuf[(slot + 1) * 32] = packh2(c2, c3);
            s[mt][0] += c0 + c1;  s2[mt][0] += c0 * c0 + c1 * c1;
            s[mt][1] += c2 + c3;  s2[mt][1] += c2 * c2 + c3 * c3;
        }
    }
#pragma unroll
    for (int off = 16; off; off >>= 1) {
#pragma unroll
        for (int mt = 0; mt < 2; mt++)
#pragma unroll
            for (int hi = 0; hi < 2; hi++) {
                s[mt][hi]  += __shfl_xor_sync(~0u, s[mt][hi], off);
                s2[mt][hi] += __shfl_xor_sync(~0u, s2[mt][hi], off);
            }
    }
    if (lane == 0) {
#pragma unroll
        for (int mt = 0; mt < 2; mt++)
#pragma unroll
            for (int hi = 0; hi < 2; hi++) {
                int g = wo * 4 + mt * 2 + hi;
                atomicAdd(&gsum[g], s[mt][hi]);
                atomicAdd(&gsq[g], s2[mt][hi]);
            }
    }
    __syncthreads();
    if (tid < GROUPS) {
        atomicAdd(&g_sum[b * GROUPS + tid], gsum[tid]);
        atomicAdd(&g_sumsq[b * GROUPS + tid], gsq[tid]);
    }
}

// ============================================================================
// Kernel 2: GroupNorm + SiLU. Reads warp-linear fp16 y (coalesced), decodes
// coordinates arithmetically, writes NCHW fp32 d_out.
// idx bits: lane[0:5) s[5:10) wid[10:13) bx[13:17) by[17:21) b[21:25)
// ============================================================================
__global__ void norm_kernel(float* __restrict__ out,
                            const float* __restrict__ gamma,
                            const float* __restrict__ beta) {
    int idx = blockIdx.x * blockDim.x + threadIdx.x;
    uint32_t u = g_y[idx];

    int lane = idx & 31, s = (idx >> 5) & 31, wid = (idx >> 10) & 7;
    int bx = (idx >> 13) & 15, by = (idx >> 17) & 15, b = idx >> 21;
    int pair = s & 1, unit = s >> 1, mt = unit >> 3, nt = unit & 7;
    int wo = wid & 1, wn = wid >> 1, g2 = lane >> 2, qp = lane & 3;

    int o = wo * 32 + mt * 16 + pair * 8 + g2;
    int g = o >> 3;
    int gh = by * 16 + wn * 4 + (nt >> 1);
    int gw = bx * 16 + (nt & 1) * 8 + 2 * qp;

    const float invN = 1.0f / (8.0f * HH * WW);
    float mean = g_sum[b * GROUPS + g] * invN;
    float var = g_sumsq[b * GROUPS + g] * invN - mean * mean;
    float istd = rsqrtf(var + 1e-5f);
    float ga = gamma[o], be = beta[o];

    float2 f = __half22float2(*(__half2*)&u);
    float t0 = (f.x - mean) * istd * ga + be;
    float t1 = (f.y - mean) * istd * ga + be;
    float2 r;
    r.x = t0 / (1.0f + __expf(-t0));
    r.y = t1 / (1.0f + __expf(-t1));
    *(float2*)(out + ((long long)(b * 64 + o) * HW + gh * WW + gw)) = r;
}

// ============================================================================
extern "C" void kernel_launch(void* const* d_in, const int* in_sizes, int n_in,
                              void* d_out, int out_size) {
    const float* x     = (const float*)d_in[0];
    const float* mod   = (const float*)d_in[1];
    const float* kmod  = (const float*)d_in[2];
    const float* cw    = (const float*)d_in[3];
    const float* gamma = (const float*)d_in[4];
    const float* beta  = (const float*)d_in[5];
    float* out = (float*)d_out;

    cudaFuncSetAttribute(conv_kernel,
                         cudaFuncAttributeMaxDynamicSharedMemorySize, SMEM_BYTES);

    weight_kernel<<<dim3(O, B), 64>>>(mod, kmod, cw);
    conv_kernel<<<dim3(16, 16, B), 256, SMEM_BYTES>>>(x);
    norm_kernel<<<(B * O * HW / 2) / 256, 256>>>(out, gamma, beta);
}

// round 15
// speedup vs baseline: 1.3860x; 1.0311x over previous
#include <cuda_runtime.h>
#include <cuda_fp16.h>
#include <cstdint>

#define HH 256
#define WW 256
#define HW 65536
#define C 64
#define O 64
#define B 16
#define NK 4
#define GROUPS 8

#define SMEM_BYTES (324 * 128)   // [px 0..323][64ch fp16] swizzled rows = 41472

// ---- scratch ----
__device__ __half g_wt[B * 9 * O * C];          // fp16 weights, fragment-ordered
__device__ uint32_t g_y[(B * O * HW) / 2];      // packed half2 y, warp-linear layout
__device__ float g_sum[B * GROUPS];
__device__ float g_sumsq[B * GROUPS];

__device__ __forceinline__ void mma_f16(float* d, const uint32_t* a,
                                        uint32_t b0, uint32_t b1) {
    asm("mma.sync.aligned.m16n8k16.row.col.f32.f16.f16.f32 "
        "{%0,%1,%2,%3}, {%4,%5,%6,%7}, {%8,%9}, {%0,%1,%2,%3};"
        : "+f"(d[0]), "+f"(d[1]), "+f"(d[2]), "+f"(d[3])
        : "r"(a[0]), "r"(a[1]), "r"(a[2]), "r"(a[3]), "r"(b0), "r"(b1));
}
__device__ __forceinline__ void ldmatrix_x4(uint32_t* r, uint32_t addr) {
    asm volatile("ldmatrix.sync.aligned.m8n8.x4.shared.b16 {%0,%1,%2,%3}, [%4];"
                 : "=r"(r[0]), "=r"(r[1]), "=r"(r[2]), "=r"(r[3]) : "r"(addr));
}
__device__ __forceinline__ uint32_t packh2(float a, float b) {
    __half2 h = __floats2half2_rn(a, b);
    return *(uint32_t*)&h;
}

// ============================================================================
// Kernel 0: softmax mix + modulate + demodulate -> fp16 fragment-ordered g_wt.
// Layout (halves): [b][tap][wo(2)][kt(4)][mt(2)][lane(32)][pos(8)]
// ============================================================================
__global__ void weight_kernel(const float* __restrict__ mod,
                              const float* __restrict__ kmod,
                              const float* __restrict__ cw) {
    int o = blockIdx.x, b = blockIdx.y, i = threadIdx.x;

    float k0 = kmod[b*NK], k1 = kmod[b*NK+1], k2 = kmod[b*NK+2], k3 = kmod[b*NK+3];
    float mx = fmaxf(fmaxf(k0, k1), fmaxf(k2, k3));
    float e0 = __expf(k0-mx), e1 = __expf(k1-mx), e2 = __expf(k2-mx), e3 = __expf(k3-mx);
    float inv = 1.0f / (e0+e1+e2+e3);
    float a0 = e0*inv, a1 = e1*inv, a2 = e2*inv, a3 = e3*inv;
    float mi = mod[b*C + i] + 1.0f;

    float wv[9], ss = 0.0f;
#pragma unroll
    for (int k = 0; k < 9; k++) {
        int base = (o*C + i)*9 + k;
        const int st = O*C*9;
        float v = a0*cw[base] + a1*cw[st+base] + a2*cw[2*st+base] + a3*cw[3*st+base];
        v *= mi;
        wv[k] = v; ss += v*v;
    }
#pragma unroll
    for (int off = 16; off; off >>= 1) ss += __shfl_xor_sync(~0u, ss, off);
    __shared__ float sh[2];
    if ((i & 31) == 0) sh[i>>5] = ss;
    __syncthreads();
    float innorm = rsqrtf(fmaxf(sh[0] + sh[1], 1e-8f));

    int wo = o >> 5, m5 = o & 31, mt = m5 >> 4, row = m5 & 15;
    int kt = i >> 4, kk = i & 15;
    int rA = ((kk >= 8) ? 2 : 0) + ((row >= 8) ? 1 : 0);
    int lane = ((row & 7) << 2) | ((kk & 7) >> 1);
    int pos = rA * 2 + (kk & 1);

#pragma unroll
    for (int k = 0; k < 9; k++) {
        long long idx = (((((long long)(b*9 + k)*2 + wo)*4 + kt)*2 + mt)*32 + lane)*8 + pos;
        g_wt[idx] = __float2half_rn(wv[k] * innorm);
    }

    if (o == 0 && i < GROUPS) { g_sum[b*GROUPS+i] = 0.0f; g_sumsq[b*GROUPS+i] = 0.0f; }
}

// ============================================================================
// Kernel 1: fp16 tensor-core conv. x tile as [px][64ch] swizzled 128B rows;
// B fragments via ldmatrix.x4 (additive swizzled addressing — no alignment
// assumptions); A frags via LDG.128; barrier-free mainloop; fp16 warp-linear
// y stores. grid (16,16,B), 256 thr = 8 warps, 2 CTA/SM.
// ============================================================================
__global__ void __launch_bounds__(256, 2)
conv_kernel(const float* __restrict__ x) {
    extern __shared__ char smem[];
    __shared__ float gsum[GROUPS], gsq[GROUPS];
    uint32_t xsb;
    asm("{ .reg .u64 t; cvta.to.shared.u64 t, %1; cvt.u32.u64 %0, t; }"
        : "=r"(xsb) : "l"((void*)smem));

    int b = blockIdx.z;
    int h0 = blockIdx.y * 16, w0 = blockIdx.x * 16;
    int tid = threadIdx.x, wid = tid >> 5, lane = tid & 31;
    int wo = wid & 1;            // O half
    int wn = wid >> 1;           // pixel quarter: tile rows 4*wn..4*wn+3
    int r8 = lane & 7;           // ldmatrix row within 8-px group
    int gb = (lane >> 3) & 1;    // ldmatrix k-chunk parity (b0/b1)
    int mhi = lane >> 4;         // ldmatrix matrix-pair select (nt / nt+1)

    if (tid < GROUPS) { gsum[tid] = 0.0f; gsq[tid] = 0.0f; }

    // ---- stage x tile: [px][64ch] fp16, chunk-swizzled, zero padded ----
    const float* xb = x + (long long)b * C * HW;
    for (int u = tid; u < 2592; u += 256) {
        int j = u / 324;              // channel chunk (8 ch)
        int px = u - j * 324;
        int rr = px / 18, cc = px - rr * 18;
        int gh = h0 + rr - 1, gw = w0 + cc - 1;
        float f[8];
        if ((unsigned)gh < HH && (unsigned)gw < WW) {
            const float* p = xb + (8 * j) * HW + gh * WW + gw;
#pragma unroll
            for (int i = 0; i < 8; i++) f[i] = p[i * HW];
        } else {
#pragma unroll
            for (int i = 0; i < 8; i++) f[i] = 0.0f;
        }
        uint32_t dst = xsb + (px << 7) + ((j ^ (px & 7)) << 4);
        asm volatile("st.shared.v4.b32 [%0], {%1,%2,%3,%4};"
                     :: "r"(dst), "r"(packh2(f[0], f[1])), "r"(packh2(f[2], f[3])),
                        "r"(packh2(f[4], f[5])), "r"(packh2(f[6], f[7])) : "memory");
    }
    __syncthreads();   // the ONLY barrier before epilogue

    float acc[2][8][4];
#pragma unroll
    for (int mt = 0; mt < 2; mt++)
#pragma unroll
        for (int nt = 0; nt < 8; nt++)
#pragma unroll
            for (int r = 0; r < 4; r++) acc[mt][nt][r] = 0.0f;

    // per-lane base pixel for each nt-pair (ntp): nt = 2*ntp + mhi
    int px0[4];
#pragma unroll
    for (int ntp = 0; ntp < 4; ntp++) {
        int nt = 2 * ntp + mhi;
        px0[ntp] = (wn * 4 + (nt >> 1)) * 18 + (nt & 1) * 8 + r8;
    }

    // A fragment base: uint4 index = ((((b*9+tap)*2+wo)*4+kt)*2+mt)*32 + lane
    const uint4* wf = (const uint4*)g_wt + ((b * 9 * 2 + wo) * 8) * 32 + lane;

#pragma unroll 1
    for (int tap = 0; tap < 9; tap++) {
        int kh = tap / 3, kw = tap - kh * 3;
        int dpx = kh * 18 + kw;
        const uint4* a_base = wf + (tap * 16) * 32;

        uint32_t pxb[4];
        int pxl[4];
#pragma unroll
        for (int ntp = 0; ntp < 4; ntp++) {
            int px = px0[ntp] + dpx;
            pxb[ntp] = xsb + (px << 7);
            pxl[ntp] = px & 7;
        }

#pragma unroll
        for (int kt = 0; kt < 4; kt++) {
            uint4 af0 = a_base[(kt * 2 + 0) * 32];
            uint4 af1 = a_base[(kt * 2 + 1) * 32];
            int cb = kt * 2 + gb;
#pragma unroll
            for (int ntp = 0; ntp < 4; ntp++) {
                uint32_t br[4];
                ldmatrix_x4(br, pxb[ntp] + (uint32_t)((cb ^ pxl[ntp]) << 4));
                mma_f16(acc[0][2 * ntp],     (const uint32_t*)&af0, br[0], br[1]);
                mma_f16(acc[1][2 * ntp],     (const uint32_t*)&af1, br[0], br[1]);
                mma_f16(acc[0][2 * ntp + 1], (const uint32_t*)&af0, br[2], br[3]);
                mma_f16(acc[1][2 * ntp + 1], (const uint32_t*)&af1, br[2], br[3]);
            }
        }
    }

    // ---- store y (fp16, warp-linear coalesced) + GN partial stats ----
    int cta_lin = (b * 16 + blockIdx.y) * 16 + blockIdx.x;
    uint32_t* ybuf = g_y + ((long long)cta_lin * 8 + wid) * 1024 + lane;
    float s[2][2] = {{0, 0}, {0, 0}}, s2[2][2] = {{0, 0}, {0, 0}};
#pragma unroll
    for (int mt = 0; mt < 2; mt++) {
#pragma unroll
        for (int nt = 0; nt < 8; nt++) {
            int slot = (mt * 8 + nt) * 2;
            float c0 = acc[mt][nt][0], c1 = acc[mt][nt][1];
            float c2 = acc[mt][nt][2], c3 = acc[mt][nt][3];
            ybuf[slot * 32] = packh2(c0, c1);
            ybuf[(slot + 1) * 32] = packh2(c2, c3);
            s[mt][0] += c0 + c1;  s2[mt][0] += c0 * c0 + c1 * c1;
            s[mt][1] += c2 + c3;  s2[mt][1] += c2 * c2 + c3 * c3;
        }
    }
#pragma unroll
    for (int off = 16; off; off >>= 1) {
#pragma unroll
        for (int mt = 0; mt < 2; mt++)
#pragma unroll
            for (int hi = 0; hi < 2; hi++) {
                s[mt][hi]  += __shfl_xor_sync(~0u, s[mt][hi], off);
                s2[mt][hi] += __shfl_xor_sync(~0u, s2[mt][hi], off);
            }
    }
    if (lane == 0) {
#pragma unroll
        for (int mt = 0; mt < 2; mt++)
#pragma unroll
            for (int hi = 0; hi < 2; hi++) {
                int g = wo * 4 + mt * 2 + hi;
                atomicAdd(&gsum[g], s[mt][hi]);
                atomicAdd(&gsq[g], s2[mt][hi]);
            }
    }
    __syncthreads();
    if (tid < GROUPS) {
        atomicAdd(&g_sum[b * GROUPS + tid], gsum[tid]);
        atomicAdd(&g_sumsq[b * GROUPS + tid], gsq[tid]);
    }
}

// ============================================================================
// Kernel 2: GroupNorm + SiLU. Reads warp-linear fp16 y (coalesced), decodes
// coordinates arithmetically, writes NCHW fp32 d_out.
// idx bits: lane[0:5) s[5:10) wid[10:13) bx[13:17) by[17:21) b[21:25)
// ============================================================================
__global__ void norm_kernel(float* __restrict__ out,
                            const float* __restrict__ gamma,
                            const float* __restrict__ beta) {
    int idx = blockIdx.x * blockDim.x + threadIdx.x;
    uint32_t u = g_y[idx];

    int lane = idx & 31, s = (idx >> 5) & 31, wid = (idx >> 10) & 7;
    int bx = (idx >> 13) & 15, by = (idx >> 17) & 15, b = idx >> 21;
    int pair = s & 1, unit = s >> 1, mt = unit >> 3, nt = unit & 7;
    int wo = wid & 1, wn = wid >> 1, g2 = lane >> 2, qp = lane & 3;

    int o = wo * 32 + mt * 16 + pair * 8 + g2;
    int g = o >> 3;
    int gh = by * 16 + wn * 4 + (nt >> 1);
    int gw = bx * 16 + (nt & 1) * 8 + 2 * qp;

    const float invN = 1.0f / (8.0f * HH * WW);
    float mean = g_sum[b * GROUPS + g] * invN;
    float var = g_sumsq[b * GROUPS + g] * invN - mean * mean;
    float istd = rsqrtf(var + 1e-5f);
    float ga = gamma[o], be = beta[o];

    float2 f = __half22float2(*(__half2*)&u);
    float t0 = (f.x - mean) * istd * ga + be;
    float t1 = (f.y - mean) * istd * ga + be;
    float2 r;
    r.x = t0 / (1.0f + __expf(-t0));
    r.y = t1 / (1.0f + __expf(-t1));
    *(float2*)(out + ((long long)(b * 64 + o) * HW + gh * WW + gw)) = r;
}

// ============================================================================
extern "C" void kernel_launch(void* const* d_in, const int* in_sizes, int n_in,
                              void* d_out, int out_size) {
    const float* x     = (const float*)d_in[0];
    const float* mod   = (const float*)d_in[1];
    const float* kmod  = (const float*)d_in[2];
    const float* cw    = (const float*)d_in[3];
    const float* gamma = (const float*)d_in[4];
    const float* beta  = (const float*)d_in[5];
    float* out = (float*)d_out;

    cudaFuncSetAttribute(conv_kernel,
                         cudaFuncAttributeMaxDynamicSharedMemorySize, SMEM_BYTES);

    weight_kernel<<<dim3(O, B), 64>>>(mod, kmod, cw);
    conv_kernel<<<dim3(16, 16, B), 256, SMEM_BYTES>>>(x);
    norm_kernel<<<(B * O * HW / 2) / 256, 256>>>(out, gamma, beta);
}